// round 2
// baseline (speedup 1.0000x reference)
#include <cuda_runtime.h>

#define G 8
#define NB 8192
#define THREADS 256

// Wk transposed: [h][c] = Wk[c][h], 256x512 floats
__device__ float g_WkT[256 * 512];

__global__ void wkT_kernel(const float* __restrict__ Wk) {
    int idx = blockIdx.x * blockDim.x + threadIdx.x;
    if (idx < 512 * 256) {
        int c = idx >> 8;      // 0..511
        int h = idx & 255;     // 0..255
        g_WkT[h * 512 + c] = Wk[idx];
    }
}

// Dynamic smem (floats):
//   bufA : [512][G]  (x concat, later wn)      4096 f
//   eq   : [512][G]  (ee in [0:256), q in [256:512)) -> later overlaid by kq [G][512]
//   sc   : [G][64]                               512 f
//   qbk  : [G]                                     8 f
#define SMEM_FLOATS (4096 + 4096 + 512 + 8 + 8)
#define SMEM_BYTES (SMEM_FLOATS * 4)

__global__ __launch_bounds__(256, 6)
void superedge_kernel(
    const float* __restrict__ mnode0, const float* __restrict__ mnode1,
    const float* __restrict__ dnode0, const float* __restrict__ dnode1,
    const float* __restrict__ mrel0,  const float* __restrict__ drel0,
    const float* __restrict__ W_edge, const float* __restrict__ b_edge,
    const float* __restrict__ Wq,     const float* __restrict__ bq,
    const float* __restrict__ bk,
    const float* __restrict__ Wv,     const float* __restrict__ bv,
    float* __restrict__ out)
{
    extern __shared__ float smem[];
    float* bufA = smem;                 // [512][G]  x, later wn
    float* ee_s = bufA + 512 * G;       // [256][G]
    float* q_s  = ee_s + 256 * G;       // [256][G]
    float* kq_s = ee_s;                 // OVERLAY: [G][512] after q is dead
    float* sc_s = q_s + 256 * G;        // [G][64]
    float* qbk_s = sc_s + G * 64;       // [G]

    const int tid = threadIdx.x;
    const int b0 = blockIdx.x * G;
    const int w = tid >> 5, lane = tid & 31;

    // ---------------- Phase 1: x = [mnode0 | dnode0] into bufA[c][g]
    #pragma unroll
    for (int g = 0; g < G; g++) {
        int b = b0 + g;
        bufA[tid * G + g]         = mnode0[(size_t)b * 256 + tid];
        bufA[(tid + 256) * G + g] = dnode0[(size_t)b * 256 + tid];
    }
    __syncthreads();

    float acc[G];

    // ---------------- Phase 2: edge_emb[h] = relu(x @ W_edge + b_edge), h = tid
    {
        float bias = b_edge[tid];
        #pragma unroll
        for (int g = 0; g < G; g++) acc[g] = bias;
        const float* Wcol = W_edge + tid;
        #pragma unroll 4
        for (int c = 0; c < 512; c++) {
            float wv = Wcol[c << 8];
            float4 xa = *(const float4*)&bufA[c * G + 0];
            float4 xb = *(const float4*)&bufA[c * G + 4];
            acc[0] += xa.x * wv; acc[1] += xa.y * wv;
            acc[2] += xa.z * wv; acc[3] += xa.w * wv;
            acc[4] += xb.x * wv; acc[5] += xb.y * wv;
            acc[6] += xb.z * wv; acc[7] += xb.w * wv;
        }
        #pragma unroll
        for (int g = 0; g < G; g++) {
            float v = fmaxf(acc[g], 0.0f);
            ee_s[tid * G + g] = v;
            out[(size_t)(b0 + g) * 512 + tid] = v;   // first half of output
        }
    }
    __syncthreads();

    // ---------------- Phase 3: q[h] = edge_emb @ Wq + bq, h = tid
    {
        float bias = bq[tid];
        #pragma unroll
        for (int g = 0; g < G; g++) acc[g] = bias;
        const float* Wcol = Wq + tid;
        #pragma unroll 4
        for (int c = 0; c < 256; c++) {
            float wv = Wcol[c << 8];
            float4 xa = *(const float4*)&ee_s[c * G + 0];
            float4 xb = *(const float4*)&ee_s[c * G + 4];
            acc[0] += xa.x * wv; acc[1] += xa.y * wv;
            acc[2] += xa.z * wv; acc[3] += xa.w * wv;
            acc[4] += xb.x * wv; acc[5] += xb.y * wv;
            acc[6] += xb.z * wv; acc[7] += xb.w * wv;
        }
        #pragma unroll
        for (int g = 0; g < G; g++) q_s[tid * G + g] = acc[g];
    }
    __syncthreads();

    // ---------------- qbk[g] = q_g . bk   (warp w handles g = w)
    {
        float p = 0.0f;
        #pragma unroll
        for (int j = 0; j < 8; j++) {
            int h = lane + (j << 5);
            p += q_s[h * G + w] * bk[h];
        }
        #pragma unroll
        for (int o = 16; o; o >>= 1) p += __shfl_xor_sync(0xffffffffu, p, o);
        if (lane == 0) qbk_s[w] = p;
    }

    // ---------------- Phase 4: kq[c] = sum_h WkT[h][c] * q[h]  (reg-resident, 2 cols/thread)
    float kqa[16];
    {
        #pragma unroll
        for (int i = 0; i < 16; i++) kqa[i] = 0.0f;
        const float* Wcol0 = g_WkT + tid;        // col c = tid
        const float* Wcol1 = g_WkT + tid + 256;  // col c = tid + 256
        #pragma unroll 2
        for (int h = 0; h < 256; h++) {
            float w0 = Wcol0[h << 9];
            float w1 = Wcol1[h << 9];
            float4 qa = *(const float4*)&q_s[h * G + 0];
            float4 qb = *(const float4*)&q_s[h * G + 4];
            kqa[0] += qa.x * w0; kqa[1] += qa.y * w0;
            kqa[2] += qa.z * w0; kqa[3] += qa.w * w0;
            kqa[4] += qb.x * w0; kqa[5] += qb.y * w0;
            kqa[6] += qb.z * w0; kqa[7] += qb.w * w0;
            kqa[8]  += qa.x * w1; kqa[9]  += qa.y * w1;
            kqa[10] += qa.z * w1; kqa[11] += qa.w * w1;
            kqa[12] += qb.x * w1; kqa[13] += qb.y * w1;
            kqa[14] += qb.z * w1; kqa[15] += qb.w * w1;
        }
    }
    __syncthreads();    // everyone done reading q/ee region
    #pragma unroll
    for (int g = 0; g < G; g++) {
        kq_s[g * 512 + tid]       = kqa[g];
        kq_s[g * 512 + tid + 256] = kqa[8 + g];
    }
    __syncthreads();

    // ---------------- Phase 5a: all 512 (g,n) scores in one pass
    // pair p = i*8 + w;  g = p>>6, n = p&63
    for (int i = 0; i < 64; i++) {
        int p_idx = (i << 3) + w;
        int g = p_idx >> 6;
        int n = p_idx & 63;
        int b = b0 + g;
        const float* rel;
        const float* node;
        if (n < 32) {
            rel  = mrel0  + ((size_t)b * 32 + n) * 256;
            node = mnode1 + ((size_t)b * 32 + n) * 256;
        } else {
            int n2 = n - 32;
            rel  = drel0  + ((size_t)b * 32 + n2) * 256;
            node = dnode1 + ((size_t)b * 32 + n2) * 256;
        }
        const float* kqg = kq_s + g * 512;
        float p = 0.0f;
        #pragma unroll
        for (int j = 0; j < 4; j++) {
            int c = (lane << 1) + (j << 6);
            float2 rv = *(const float2*)(rel + c);
            float2 nv = *(const float2*)(node + c);
            p += rv.x * kqg[c]       + rv.y * kqg[c + 1];
            p += nv.x * kqg[c + 256] + nv.y * kqg[c + 257];
        }
        #pragma unroll
        for (int o = 16; o; o >>= 1) p += __shfl_xor_sync(0xffffffffu, p, o);
        if (lane == 0) sc_s[(g << 6) + n] = (p + qbk_s[g]) * 0.0625f; // /sqrt(256)
    }
    __syncthreads();

    // ---------------- Phase 5b: softmax, warp w handles batch g = w
    {
        float a = sc_s[(w << 6) + lane], bb = sc_s[(w << 6) + 32 + lane];
        float m = fmaxf(a, bb);
        #pragma unroll
        for (int o = 16; o; o >>= 1) m = fmaxf(m, __shfl_xor_sync(0xffffffffu, m, o));
        float e1 = __expf(a - m), e2 = __expf(bb - m);
        float s = e1 + e2;
        #pragma unroll
        for (int o = 16; o; o >>= 1) s += __shfl_xor_sync(0xffffffffu, s, o);
        float inv = 1.0f / s;
        sc_s[(w << 6) + lane] = e1 * inv;
        sc_s[(w << 6) + 32 + lane] = e2 * inv;
    }
    __syncthreads();

    // ---------------- Phase 5c: wn[c][g] = sum_n attn * edge_nei; thread owns c = 2*tid
    {
        int c = tid * 2;
        bool isNode = (c >= 256);
        int cc = isNode ? c - 256 : c;
        const float* am = isNode ? mnode1 : mrel0;   // n < 32
        const float* ad = isNode ? dnode1 : drel0;   // n >= 32
        for (int g = 0; g < G; g++) {
            int b = b0 + g;
            const float* pm = am + (size_t)b * 32 * 256 + cc;
            const float* pd = ad + (size_t)b * 32 * 256 + cc;
            const float* pr = sc_s + (g << 6);
            float ax = 0.0f, ay = 0.0f;
            #pragma unroll 8
            for (int n = 0; n < 32; n++) {
                float w0 = pr[n];
                float2 vv = *(const float2*)(pm + n * 256);
                ax += w0 * vv.x; ay += w0 * vv.y;
            }
            #pragma unroll 8
            for (int n = 0; n < 32; n++) {
                float w0 = pr[n + 32];
                float2 vv = *(const float2*)(pd + n * 256);
                ax += w0 * vv.x; ay += w0 * vv.y;
            }
            bufA[c * G + g] = ax;
            bufA[(c + 1) * G + g] = ay;
        }
    }
    __syncthreads();

    // ---------------- Phase 6: local_edge[h] = wn @ Wv + bv, h = tid
    {
        float bias = bv[tid];
        #pragma unroll
        for (int g = 0; g < G; g++) acc[g] = bias;
        const float* Wcol = Wv + tid;
        #pragma unroll 4
        for (int c = 0; c < 512; c++) {
            float wv = Wcol[c << 8];
            float4 xa = *(const float4*)&bufA[c * G + 0];
            float4 xb = *(const float4*)&bufA[c * G + 4];
            acc[0] += xa.x * wv; acc[1] += xa.y * wv;
            acc[2] += xa.z * wv; acc[3] += xa.w * wv;
            acc[4] += xb.x * wv; acc[5] += xb.y * wv;
            acc[6] += xb.z * wv; acc[7] += xb.w * wv;
        }
        #pragma unroll
        for (int g = 0; g < G; g++)
            out[(size_t)(b0 + g) * 512 + 256 + tid] = acc[g];  // second half
    }
}

extern "C" void kernel_launch(void* const* d_in, const int* in_sizes, int n_in,
                              void* d_out, int out_size) {
    const float* mnode0 = (const float*)d_in[0];
    const float* mnode1 = (const float*)d_in[1];
    const float* dnode0 = (const float*)d_in[2];
    const float* dnode1 = (const float*)d_in[3];
    const float* mrel0  = (const float*)d_in[4];
    const float* drel0  = (const float*)d_in[5];
    const float* W_edge = (const float*)d_in[6];
    const float* b_edge = (const float*)d_in[7];
    const float* Wq     = (const float*)d_in[8];
    const float* bq     = (const float*)d_in[9];
    const float* Wk     = (const float*)d_in[10];
    const float* bk     = (const float*)d_in[11];
    const float* Wv     = (const float*)d_in[12];
    const float* bv     = (const float*)d_in[13];
    float* out = (float*)d_out;

    cudaFuncSetAttribute(superedge_kernel,
                         cudaFuncAttributeMaxDynamicSharedMemorySize, SMEM_BYTES);

    wkT_kernel<<<512, 256>>>(Wk);
    superedge_kernel<<<NB / G, THREADS, SMEM_BYTES>>>(
        mnode0, mnode1, dnode0, dnode1, mrel0, drel0,
        W_edge, b_edge, Wq, bq, bk, Wv, bv, out);
}

// round 3
// speedup vs baseline: 1.6425x; 1.6425x over previous
#include <cuda_runtime.h>
#include <math_constants.h>

#define G 8
#define NB 8192
#define THREADS 256

// Wk transposed: [h][c] = Wk[c][h], 256x512 floats
__device__ float g_WkT[256 * 512];

__global__ void wkT_kernel(const float* __restrict__ Wk) {
    int idx = blockIdx.x * blockDim.x + threadIdx.x;
    if (idx < 512 * 256) {
        int c = idx >> 8;      // 0..511
        int h = idx & 255;     // 0..255
        g_WkT[h * 512 + c] = Wk[idx];
    }
}

// Dynamic smem (floats):
//   bufA : [512][G]  (x concat, later wn)                    4096 f
//   eq   : [512][G]  (ee [0:256), q [256:512)) -> overlay kq 4096 f
//   qbk  : [G]                                                  8 f
#define SMEM_FLOATS (4096 + 4096 + 8 + 8)
#define SMEM_BYTES (SMEM_FLOATS * 4)

// GEMV with 8 batch-accumulators and double-buffered weight prefetch.
// Wcol: column base (W + h), column stride 256 floats. xs: smem [KD][8].
template<int KD>
__device__ __forceinline__ void gemv_acc8(const float* __restrict__ Wcol,
                                          const float* __restrict__ xs,
                                          float acc[8])
{
    float wreg[8];
    #pragma unroll
    for (int j = 0; j < 8; j++) wreg[j] = __ldg(&Wcol[j << 8]);
    #pragma unroll 1
    for (int c0 = 0; c0 < KD; c0 += 8) {
        float wnxt[8];
        if (c0 + 8 < KD) {
            #pragma unroll
            for (int j = 0; j < 8; j++) wnxt[j] = __ldg(&Wcol[(c0 + 8 + j) << 8]);
        }
        #pragma unroll
        for (int j = 0; j < 8; j++) {
            float4 xa = *(const float4*)&xs[(c0 + j) * 8 + 0];
            float4 xb = *(const float4*)&xs[(c0 + j) * 8 + 4];
            float wv = wreg[j];
            acc[0] += xa.x * wv; acc[1] += xa.y * wv;
            acc[2] += xa.z * wv; acc[3] += xa.w * wv;
            acc[4] += xb.x * wv; acc[5] += xb.y * wv;
            acc[6] += xb.z * wv; acc[7] += xb.w * wv;
        }
        #pragma unroll
        for (int j = 0; j < 8; j++) wreg[j] = wnxt[j];
    }
}

__global__ __launch_bounds__(256, 4)
void superedge_kernel(
    const float* __restrict__ mnode0, const float* __restrict__ mnode1,
    const float* __restrict__ dnode0, const float* __restrict__ dnode1,
    const float* __restrict__ mrel0,  const float* __restrict__ drel0,
    const float* __restrict__ W_edge, const float* __restrict__ b_edge,
    const float* __restrict__ Wq,     const float* __restrict__ bq,
    const float* __restrict__ bk,
    const float* __restrict__ Wv,     const float* __restrict__ bv,
    float* __restrict__ out)
{
    extern __shared__ float smem[];
    float* bufA = smem;                 // [512][G]  x, later wn
    float* ee_s = bufA + 512 * G;       // [256][G]
    float* q_s  = ee_s + 256 * G;       // [256][G]
    float* kq_s = ee_s;                 // OVERLAY [G][512] (ee+q dead)
    float* qbk_s = q_s + 256 * G;       // [G]

    const int tid = threadIdx.x;
    const int b0 = blockIdx.x * G;
    const int w = tid >> 5, lane = tid & 31;

    // ---------------- Phase 1: x = [mnode0 | dnode0] -> bufA[c][g]
    #pragma unroll
    for (int g = 0; g < G; g++) {
        int b = b0 + g;
        bufA[tid * G + g]         = mnode0[(size_t)b * 256 + tid];
        bufA[(tid + 256) * G + g] = dnode0[(size_t)b * 256 + tid];
    }
    __syncthreads();

    float acc[8];

    // ---------------- Phase 2: edge_emb[h=tid] = relu(x @ W_edge + b_edge)
    {
        float bias = b_edge[tid];
        #pragma unroll
        for (int g = 0; g < G; g++) acc[g] = bias;
        gemv_acc8<512>(W_edge + tid, bufA, acc);
        #pragma unroll
        for (int g = 0; g < G; g++) {
            float v = fmaxf(acc[g], 0.0f);
            ee_s[tid * G + g] = v;
            out[(size_t)(b0 + g) * 512 + tid] = v;   // first half of output
        }
    }
    __syncthreads();

    // ---------------- Phase 3: q[h=tid] = ee @ Wq + bq
    {
        float bias = bq[tid];
        #pragma unroll
        for (int g = 0; g < G; g++) acc[g] = bias;
        gemv_acc8<256>(Wq + tid, ee_s, acc);
        #pragma unroll
        for (int g = 0; g < G; g++) q_s[tid * G + g] = acc[g];
    }
    __syncthreads();

    // ---------------- qbk[g] = q_g . bk (warp w -> g = w)
    {
        float p = 0.0f;
        #pragma unroll
        for (int j = 0; j < 8; j++) {
            int h = lane + (j << 5);
            p += q_s[h * G + w] * bk[h];
        }
        #pragma unroll
        for (int o = 16; o; o >>= 1) p += __shfl_xor_sync(0xffffffffu, p, o);
        if (lane == 0) qbk_s[w] = p;
    }

    // ---------------- Phase 4: kq[c] = sum_h WkT[h][c] * q[h]  (2 cols/thread, prefetch d=4)
    float kqa[16];
    {
        #pragma unroll
        for (int i = 0; i < 16; i++) kqa[i] = 0.0f;
        const float* Wc0 = g_WkT + tid;        // col tid
        const float* Wc1 = g_WkT + tid + 256;  // col tid+256
        float w0b[4], w1b[4];
        #pragma unroll
        for (int j = 0; j < 4; j++) {
            w0b[j] = __ldg(&Wc0[j << 9]);
            w1b[j] = __ldg(&Wc1[j << 9]);
        }
        #pragma unroll 1
        for (int h0 = 0; h0 < 256; h0 += 4) {
            float w0n[4], w1n[4];
            if (h0 + 4 < 256) {
                #pragma unroll
                for (int j = 0; j < 4; j++) {
                    w0n[j] = __ldg(&Wc0[(h0 + 4 + j) << 9]);
                    w1n[j] = __ldg(&Wc1[(h0 + 4 + j) << 9]);
                }
            }
            #pragma unroll
            for (int j = 0; j < 4; j++) {
                int h = h0 + j;
                float4 qa = *(const float4*)&q_s[h * G + 0];
                float4 qb = *(const float4*)&q_s[h * G + 4];
                float wv0 = w0b[j], wv1 = w1b[j];
                kqa[0] += qa.x * wv0; kqa[1] += qa.y * wv0;
                kqa[2] += qa.z * wv0; kqa[3] += qa.w * wv0;
                kqa[4] += qb.x * wv0; kqa[5] += qb.y * wv0;
                kqa[6] += qb.z * wv0; kqa[7] += qb.w * wv0;
                kqa[8]  += qa.x * wv1; kqa[9]  += qa.y * wv1;
                kqa[10] += qa.z * wv1; kqa[11] += qa.w * wv1;
                kqa[12] += qb.x * wv1; kqa[13] += qb.y * wv1;
                kqa[14] += qb.z * wv1; kqa[15] += qb.w * wv1;
            }
            #pragma unroll
            for (int j = 0; j < 4; j++) { w0b[j] = w0n[j]; w1b[j] = w1n[j]; }
        }
    }
    __syncthreads();    // all reads of q/ee done before overlay write
    #pragma unroll
    for (int g = 0; g < G; g++) {
        kq_s[g * 512 + tid]       = kqa[g];
        kq_s[g * 512 + tid + 256] = kqa[8 + g];
    }
    __syncthreads();

    // ---------------- Phase 5: warp w owns batch b0+w. Online softmax, one pass.
    {
        const int b = b0 + w;
        const float* kqg = kq_s + w * 512;
        const float qbk = qbk_s[w];

        // kq cached in regs: lane covers c = 4l..4l+3 in each 128-chunk
        float4 kq0 = *(const float4*)&kqg[4 * lane];
        float4 kq1 = *(const float4*)&kqg[128 + 4 * lane];
        float4 kq2 = *(const float4*)&kqg[256 + 4 * lane];
        float4 kq3 = *(const float4*)&kqg[384 + 4 * lane];

        const float* relm  = mrel0  + (size_t)b * 32 * 256;
        const float* nodem = mnode1 + (size_t)b * 32 * 256;
        const float* reld  = drel0  + (size_t)b * 32 * 256;
        const float* noded = dnode1 + (size_t)b * 32 * 256;

        float m = -CUDART_INF_F, ssum = 0.0f;
        float wacc[16];
        #pragma unroll
        for (int j = 0; j < 16; j++) wacc[j] = 0.0f;

        #pragma unroll 1
        for (int n = 0; n < 64; n++) {
            const float* rel  = (n < 32) ? (relm  + n * 256) : (reld  + (n - 32) * 256);
            const float* node = (n < 32) ? (nodem + n * 256) : (noded + (n - 32) * 256);

            float4 r0 = *(const float4*)(rel + 4 * lane);
            float4 r1 = *(const float4*)(rel + 128 + 4 * lane);
            float4 n0 = *(const float4*)(node + 4 * lane);
            float4 n1 = *(const float4*)(node + 128 + 4 * lane);

            float p = r0.x * kq0.x + r0.y * kq0.y + r0.z * kq0.z + r0.w * kq0.w;
            p += r1.x * kq1.x + r1.y * kq1.y + r1.z * kq1.z + r1.w * kq1.w;
            p += n0.x * kq2.x + n0.y * kq2.y + n0.z * kq2.z + n0.w * kq2.w;
            p += n1.x * kq3.x + n1.y * kq3.y + n1.z * kq3.z + n1.w * kq3.w;
            #pragma unroll
            for (int o = 16; o; o >>= 1) p += __shfl_xor_sync(0xffffffffu, p, o);

            float sn = (p + qbk) * 0.0625f;   // / sqrt(256)

            if (sn > m) {                      // warp-uniform branch
                float scale = __expf(m - sn);
                ssum *= scale;
                #pragma unroll
                for (int j = 0; j < 16; j++) wacc[j] *= scale;
                m = sn;
            }
            float e = __expf(sn - m);
            ssum += e;
            // row re-read is L1-hot (entire row just loaded above)
            #pragma unroll
            for (int j = 0; j < 8; j++)
                wacc[j] += e * rel[lane + (j << 5)];
            #pragma unroll
            for (int j = 0; j < 8; j++)
                wacc[8 + j] += e * node[lane + (j << 5)];
        }

        float inv = 1.0f / ssum;
        // store wn to bufA[c][g]: c = lane+32j (rel) and 256+lane+32j (node)
        #pragma unroll
        for (int j = 0; j < 8; j++)
            bufA[(lane + (j << 5)) * G + w] = wacc[j] * inv;
        #pragma unroll
        for (int j = 0; j < 8; j++)
            bufA[(256 + lane + (j << 5)) * G + w] = wacc[8 + j] * inv;
    }
    __syncthreads();

    // ---------------- Phase 6: local_edge[h=tid] = wn @ Wv + bv
    {
        float bias = bv[tid];
        #pragma unroll
        for (int g = 0; g < G; g++) acc[g] = bias;
        gemv_acc8<512>(Wv + tid, bufA, acc);
        #pragma unroll
        for (int g = 0; g < G; g++)
            out[(size_t)(b0 + g) * 512 + 256 + tid] = acc[g];  // second half
    }
}

extern "C" void kernel_launch(void* const* d_in, const int* in_sizes, int n_in,
                              void* d_out, int out_size) {
    const float* mnode0 = (const float*)d_in[0];
    const float* mnode1 = (const float*)d_in[1];
    const float* dnode0 = (const float*)d_in[2];
    const float* dnode1 = (const float*)d_in[3];
    const float* mrel0  = (const float*)d_in[4];
    const float* drel0  = (const float*)d_in[5];
    const float* W_edge = (const float*)d_in[6];
    const float* b_edge = (const float*)d_in[7];
    const float* Wq     = (const float*)d_in[8];
    const float* bq     = (const float*)d_in[9];
    const float* Wk     = (const float*)d_in[10];
    const float* bk     = (const float*)d_in[11];
    const float* Wv     = (const float*)d_in[12];
    const float* bv     = (const float*)d_in[13];
    float* out = (float*)d_out;

    cudaFuncSetAttribute(superedge_kernel,
                         cudaFuncAttributeMaxDynamicSharedMemorySize, SMEM_BYTES);

    wkT_kernel<<<512, 256>>>(Wk);
    superedge_kernel<<<NB / G, THREADS, SMEM_BYTES>>>(
        mnode0, mnode1, dnode0, dnode1, mrel0, drel0,
        W_edge, b_edge, Wq, bq, bk, Wv, bv, out);
}